// round 2
// baseline (speedup 1.0000x reference)
#include <cuda_runtime.h>

// SequentialConv: B=8, C=64, H=192, W=256, 3x3 kernel, sequential row recurrence.
// Persistent wavefront kernel: 8 batches x 16 width-tiles = 128 CTAs (all resident),
// neighbor-only halo sync via global flags.

#define Bb 8
#define Cc 64
#define Hh 192
#define Ww 256
#define NT 16          // width tiles per batch
#define TW 16          // columns per tile
#define NTHR 128
#define RST 20         // smem row stride (18 used: w0-1 .. w0+16)

#define WSM_FLOATS (Cc * Cc * 9)
#define RBUF_FLOATS (3 * Cc * RST)
#define SMEM_FLOATS (WSM_FLOATS + RBUF_FLOATS + Cc)
#define SMEM_BYTES (SMEM_FLOATS * 4)

__device__ int g_flags[Bb * NT];

__global__ void sc_init_flags() {
    int i = threadIdx.x;
    if (i < Bb * NT) g_flags[i] = 1;  // rows 0,1 are "complete" (unchanged)
}

__global__ void __launch_bounds__(NTHR, 1) sc_main(
    const float* __restrict__ X, const float* __restrict__ Wt,
    const float* __restrict__ Bs, float* __restrict__ Out)
{
    extern __shared__ float smem[];
    float* wsm  = smem;                      // [ci][kh][kw][co]  147456 B
    float* rbuf = smem + WSM_FLOATS;         // [slot][ci][RST]   15360 B
    float* bsm  = rbuf + RBUF_FLOATS;        // [co]

    const int tile = blockIdx.x;
    const int b    = blockIdx.y;
    const int w0   = tile * TW;
    const int tid  = threadIdx.x;

    // Load weights transposed: wsm[((ci*3+kh)*3+kw)*64 + co] = W[co][ci][kh][kw]
    for (int i = tid; i < Cc * Cc * 9; i += NTHR) {
        int co = i & 63; int r = i >> 6;
        int kw = r % 3; r /= 3; int kh = r % 3; int ci = r / 3;
        wsm[((ci * 3 + kh) * 3 + kw) * Cc + co] = Wt[((co * Cc + ci) * 3 + kh) * 3 + kw];
    }
    if (tid < Cc) bsm[tid] = Bs[tid];

    const float* Xb = X   + (size_t)b * Cc * Hh * Ww;
    float*       Ob = Out + (size_t)b * Cc * Hh * Ww;

    // Init: rows 0,1 (unchanged) -> rbuf slots 0,1 (with halo from X) and copy to Out.
    for (int r = 0; r < 2; r++) {
        for (int i = tid; i < Cc * 18; i += NTHR) {
            int ci = i / 18, wi = i % 18; int w = w0 - 1 + wi;
            float v = (w >= 0 && w < Ww) ? Xb[(ci * Hh + r) * Ww + w] : 0.f;
            rbuf[(r * Cc + ci) * RST + wi] = v;
        }
        for (int i = tid; i < Cc * TW; i += NTHR) {
            int ci = i / TW, wq = i % TW;
            Ob[(ci * Hh + r) * Ww + w0 + wq] = Xb[(ci * Hh + r) * Ww + w0 + wq];
        }
    }

    // Thread -> (2 output channels, 4 output columns)
    const int co0 = (tid >> 2) * 2;      // 32 co-groups of 2
    const int wl  = (tid & 3) * 4;       // 4 w-groups of 4

    int* myflag = &g_flags[b * NT + tile];
    int* lflag  = (tile > 0)      ? &g_flags[b * NT + tile - 1] : (int*)0;
    int* rflag  = (tile < NT - 1) ? &g_flags[b * NT + tile + 1] : (int*)0;

    for (int pos = 2; pos < Hh; pos++) {
        const int s2 = pos % 3;            // orig row pos -> becomes updated row pos
        const int s0 = (pos + 1) % 3;      // == (pos-2)%3 : updated row pos-2
        const int s1 = (pos + 2) % 3;      // == (pos-1)%3 : updated row pos-1

        // Load original row `pos` (with halo) into slot s2.
        for (int i = tid; i < Cc * 18; i += NTHR) {
            int ci = i / 18, wi = i % 18; int w = w0 - 1 + wi;
            float v = (w >= 0 && w < Ww) ? Xb[(ci * Hh + pos) * Ww + w] : 0.f;
            rbuf[(s2 * Cc + ci) * RST + wi] = v;
        }
        __syncthreads();

        float acc0[4] = {0.f, 0.f, 0.f, 0.f};
        float acc1[4] = {0.f, 0.f, 0.f, 0.f};
        const float* base0 = rbuf + s0 * Cc * RST + wl;
        const float* base1 = rbuf + s1 * Cc * RST + wl;
        const float* base2 = rbuf + s2 * Cc * RST + wl;
        const float* wq    = wsm + co0;

        #pragma unroll 2
        for (int ci = 0; ci < Cc; ci++) {
            const float* rr0 = base0 + ci * RST;
            const float* rr1 = base1 + ci * RST;
            const float* rr2 = base2 + ci * RST;
            #pragma unroll
            for (int kh = 0; kh < 3; kh++) {
                const float* row = (kh == 0) ? rr0 : (kh == 1) ? rr1 : rr2;
                float in0 = row[0], in1 = row[1], in2 = row[2];
                float in3 = row[3], in4 = row[4], in5 = row[5];
                const float* wk = wq + (ci * 9 + kh * 3) * Cc;
                float2 wv0 = *(const float2*)(wk);
                float2 wv1 = *(const float2*)(wk + Cc);
                float2 wv2 = *(const float2*)(wk + 2 * Cc);
                acc0[0] += in0 * wv0.x; acc1[0] += in0 * wv0.y;
                acc0[1] += in1 * wv0.x; acc1[1] += in1 * wv0.y;
                acc0[2] += in2 * wv0.x; acc1[2] += in2 * wv0.y;
                acc0[3] += in3 * wv0.x; acc1[3] += in3 * wv0.y;
                acc0[0] += in1 * wv1.x; acc1[0] += in1 * wv1.y;
                acc0[1] += in2 * wv1.x; acc1[1] += in2 * wv1.y;
                acc0[2] += in3 * wv1.x; acc1[2] += in3 * wv1.y;
                acc0[3] += in4 * wv1.x; acc1[3] += in4 * wv1.y;
                acc0[0] += in2 * wv2.x; acc1[0] += in2 * wv2.y;
                acc0[1] += in3 * wv2.x; acc1[1] += in3 * wv2.y;
                acc0[2] += in4 * wv2.x; acc1[2] += in4 * wv2.y;
                acc0[3] += in5 * wv2.x; acc1[3] += in5 * wv2.y;
            }
        }

        // out = orig + tanh(y + bias)  (orig read from slot s2 before overwrite)
        float res0[4], res1[4];
        const float* ocb = rbuf + s2 * Cc * RST;
        float bb0 = bsm[co0], bb1 = bsm[co0 + 1];
        #pragma unroll
        for (int j = 0; j < 4; j++) {
            float o0 = ocb[co0 * RST + wl + 1 + j];
            float o1 = ocb[(co0 + 1) * RST + wl + 1 + j];
            res0[j] = o0 + tanhf(acc0[j] + bb0);
            res1[j] = o1 + tanhf(acc1[j] + bb1);
        }
        __syncthreads();   // all reads of slot s2 (orig) complete before overwrite

        // Write updated row into slot s2 (interior) and into Out.
        float* wr0 = rbuf + (s2 * Cc + co0) * RST + wl + 1;
        #pragma unroll
        for (int j = 0; j < 4; j++) { wr0[j] = res0[j]; wr0[RST + j] = res1[j]; }

        float* og = Ob + ((size_t)co0 * Hh + pos) * Ww + w0 + wl;
        *(float4*)og = make_float4(res0[0], res0[1], res0[2], res0[3]);
        *(float4*)(og + (size_t)Hh * Ww) = make_float4(res1[0], res1[1], res1[2], res1[3]);

        // Publish: all stores -> fence -> barrier -> flag release.
        __threadfence();
        __syncthreads();
        if (tid == 0) atomicExch(myflag, pos);

        // Acquire neighbors' row `pos`, then pull 1-column halos from Out (L2).
        if (tid == 0 && lflag)  { while (atomicAdd(lflag, 0) < pos) __nanosleep(40); __threadfence(); }
        if (tid == 32 && rflag) { while (atomicAdd(rflag, 0) < pos) __nanosleep(40); __threadfence(); }
        __syncthreads();

        if (tid < Cc) {
            if (lflag)
                rbuf[(s2 * Cc + tid) * RST] =
                    __ldcg(&Ob[((size_t)tid * Hh + pos) * Ww + w0 - 1]);
        } else {
            int ci = tid - Cc;
            if (rflag)
                rbuf[(s2 * Cc + ci) * RST + 17] =
                    __ldcg(&Ob[((size_t)ci * Hh + pos) * Ww + w0 + TW]);
        }
        // next iteration's __syncthreads orders these STS before compute reads
    }
}

extern "C" void kernel_launch(void* const* d_in, const int* in_sizes, int n_in,
                              void* d_out, int out_size) {
    const float* X  = (const float*)d_in[0];
    const float* Wt = (const float*)d_in[1];
    const float* Bs = (const float*)d_in[2];
    float* Out = (float*)d_out;
    (void)in_sizes; (void)n_in; (void)out_size;

    cudaFuncSetAttribute(sc_main, cudaFuncAttributeMaxDynamicSharedMemorySize, SMEM_BYTES);

    sc_init_flags<<<1, NTHR>>>();
    sc_main<<<dim3(NT, Bb), NTHR, SMEM_BYTES>>>(X, Wt, Bs, Out);
}